// round 7
// baseline (speedup 1.0000x reference)
#include <cuda_runtime.h>
#include <stdint.h>

#define MDIM  41
#define HALF  20
#define NPAIR 1261                 // (m,n) pairs with |m+n| <= 20
#define NTRIP (NPAIR * MDIM)       // 51701 triplets
#define BATCH 128
#define TPB   256
#define PPB   32                   // pairs per block (8 warps x 4)
#define PPW   4                    // pairs per warp
#define NCPLX (26470912LL)         // 128*2*2*51701 (real-parts buffer, floats)
#define NFLT  (52941824LL)         // full interleaved-complex float count

// prefix of pair counts: rows 0..40, count(i) = 41 - |i-20|
__device__ __forceinline__ int pair_base(int i) {
    return (i <= HALF) ? (i * (i + 41)) >> 1
                       : 651 + (((102 - i) * (i - 21)) >> 1);
}

__device__ __forceinline__ void decode_pair(int p, int& im, int& in_, int& imn) {
    int i;
    if (p < 651) {
        i = (int)((-41.0f + __fsqrt_rn(1681.0f + 8.0f * (float)p)) * 0.5f);
    } else {
        float q = (float)(p - 651);
        i = 21 + (int)((81.0f - __fsqrt_rn(6561.0f - 8.0f * q)) * 0.5f);
    }
    if (i < 0) i = 0;
    if (i > 40) i = 40;
    while (i < 40 && pair_base(i + 1) <= p) i++;
    while (i > 0 && pair_base(i) > p) i--;
    int m   = i - HALF;
    int off = p - pair_base(i);
    int nlo = (m > 0) ? -HALF : -HALF - m;
    int n   = nlo + off;
    im  = i;
    in_ = n + HALF;
    imn = m + n + HALF;
}

// ---------------- MODE 1: real-parts-only layout (primary) ----------------
// out viewed as float2: element (b*2+nm)*NTRIP + t = {feat1.re, feat2.re}
__global__ void __launch_bounds__(TPB)
sofeat_pair_kernel(const float* __restrict__ Er,
                   const float* __restrict__ Ei,
                   float2* __restrict__ out2)
{
    __shared__ float4 sE[MDIM];      // (re0, im0, re1, im1)
    __shared__ float  sT1[MDIM];
    __shared__ float2 sT2[MDIM];
    __shared__ float4 sE1[PPB];      // (e1x0, e1y0, e1x1, e1y1)

    const int tid  = threadIdx.x;
    const int warp = tid >> 5;
    const int lane = tid & 31;
    const int b    = blockIdx.y;
    const int p_lo = blockIdx.x * PPB;

    // phase 0: E[b], term1/term2 (threads 0..40)
    if (tid < MDIM) {
        const float* er = Er + (size_t)b * (MDIM * 2);
        const float* ei = Ei + (size_t)b * (MDIM * 2);
        int i = tid, j = 40 - tid;
        float4 e = make_float4(er[2*i], ei[2*i], er[2*i+1], ei[2*i+1]);
        float4 q = make_float4(er[2*j], ei[2*j], er[2*j+1], ei[2*j+1]);
        sE[i]  = e;
        sT1[i] = e.x*e.x + e.y*e.y + e.z*e.z + e.w*e.w;
        float2 t2;
        t2.x = e.x*q.x - e.y*q.y + e.z*q.z - e.w*q.w;
        t2.y = e.x*q.y + e.y*q.x + e.z*q.w + e.w*q.z;
        sT2[i] = t2;
    }
    __syncthreads();

    // phase 1: E1 per pair in window (threads 0..PPB-1)
    if (tid < PPB && p_lo + tid < NPAIR) {
        int im, in_, imn;
        decode_pair(p_lo + tid, im, in_, imn);
        float4 a = sE[im], c = sE[in_], d = sE[imn];
        float abx0 = a.x*c.x - a.y*c.y;
        float aby0 = a.x*c.y + a.y*c.x;
        float abx1 = a.z*c.z - a.w*c.w;
        float aby1 = a.z*c.w + a.w*c.z;
        sE1[tid] = make_float4(abx0*d.x + aby0*d.y,   // e1x0
                               aby0*d.x - abx0*d.y,   // e1y0
                               abx1*d.z + aby1*d.w,   // e1x1
                               aby1*d.z - abx1*d.w);  // e1y1
    }
    __syncthreads();

    // per-lane k registers: kA = lane (0..31), kB = lane+32 (lane<9)
    const float  t1a = sT1[lane];
    const float2 t2a = sT2[lane];
    float  t1b = 0.f;
    float2 t2b = make_float2(0.f, 0.f);
    const bool tail = (lane < MDIM - 32);   // 9 lanes
    if (tail) { t1b = sT1[32 + lane]; t2b = sT2[32 + lane]; }

    const size_t base0 = (size_t)(b * 2 + 0) * NTRIP;   // float2 elements
    const size_t base1 = (size_t)(b * 2 + 1) * NTRIP;

    #pragma unroll
    for (int j = 0; j < PPW; j++) {
        const int lp = warp * PPW + j;
        const int p  = p_lo + lp;
        if (p >= NPAIR) break;

        const float4 e1 = sE1[lp];          // broadcast
        const size_t ta = (size_t)p * MDIM + lane;

        out2[base0 + ta] = make_float2(e1.x * t1a, e1.x*t2a.x + e1.y*t2a.y);
        out2[base1 + ta] = make_float2(e1.z * t1a, e1.z*t2a.x + e1.w*t2a.y);
        if (tail) {
            const size_t tb = ta + 32;
            out2[base0 + tb] = make_float2(e1.x * t1b, e1.x*t2b.x + e1.y*t2b.y);
            out2[base1 + tb] = make_float2(e1.z * t1b, e1.z*t2b.x + e1.w*t2b.y);
        }
    }
}

// ---------------- MODE 0 fallback: interleaved complex ----------------
#define TPT   4
#define TBLK  (TPB * TPT)
#define MAXP  28
__global__ void __launch_bounds__(TPB)
sofeat_full_kernel(const float* __restrict__ Er,
                   const float* __restrict__ Ei,
                   float* __restrict__ out,
                   size_t cap_f)
{
    __shared__ float4 sE[MDIM];
    __shared__ float  sT1[MDIM];
    __shared__ float2 sT2[MDIM];
    __shared__ float4 sE1[MAXP];

    const int tid  = threadIdx.x;
    const int b    = blockIdx.y;
    const int t_lo = blockIdx.x * TBLK;
    const int t_hi = (t_lo + TBLK < NTRIP) ? t_lo + TBLK : NTRIP;
    const int p_lo = t_lo / MDIM;
    const int np   = (t_hi - 1) / MDIM - p_lo + 1;

    if (tid < MDIM) {
        const float* er = Er + (size_t)b * (MDIM * 2);
        const float* ei = Ei + (size_t)b * (MDIM * 2);
        int i = tid, j = 40 - tid;
        float4 e = make_float4(er[2*i], ei[2*i], er[2*i+1], ei[2*i+1]);
        float4 q = make_float4(er[2*j], ei[2*j], er[2*j+1], ei[2*j+1]);
        sE[i]  = e;
        sT1[i] = e.x*e.x + e.y*e.y + e.z*e.z + e.w*e.w;
        float2 t2;
        t2.x = e.x*q.x - e.y*q.y + e.z*q.z - e.w*q.w;
        t2.y = e.x*q.y + e.y*q.x + e.z*q.w + e.w*q.z;
        sT2[i] = t2;
    }
    __syncthreads();

    if (tid < np) {
        int im, in_, imn;
        decode_pair(p_lo + tid, im, in_, imn);
        float4 a = sE[im], c = sE[in_], d = sE[imn];
        float abx0 = a.x*c.x - a.y*c.y;
        float aby0 = a.x*c.y + a.y*c.x;
        float abx1 = a.z*c.z - a.w*c.w;
        float aby1 = a.z*c.w + a.w*c.z;
        sE1[tid] = make_float4(abx0*d.x + aby0*d.y, aby0*d.x - abx0*d.y,
                               abx1*d.z + aby1*d.w, aby1*d.z - abx1*d.w);
    }
    __syncthreads();

    int t = t_lo + tid;
    #pragma unroll
    for (int jj = 0; jj < TPT; jj++, t += TPB) {
        if (t >= t_hi) break;
        const unsigned p  = (unsigned)t / MDIM;
        const int      kk = t - (int)p * MDIM;
        const float4 e1 = sE1[p - (unsigned)p_lo];
        const float  t1 = sT1[kk];
        const float2 t2 = sT2[kk];
        float4 v0 = make_float4(e1.x * t1, e1.y * t1,
                                e1.x*t2.x + e1.y*t2.y, e1.x*t2.y - e1.y*t2.x);
        float4 v1 = make_float4(e1.z * t1, e1.w * t1,
                                e1.z*t2.x + e1.w*t2.y, e1.z*t2.y - e1.w*t2.x);
        size_t f0 = (size_t)(b * 2 + 0) * (4 * (size_t)NTRIP) + 4 * (size_t)t;
        size_t f1 = (size_t)(b * 2 + 1) * (4 * (size_t)NTRIP) + 4 * (size_t)t;
        if (f0 + 4 <= cap_f) {
            *reinterpret_cast<float2*>(out + f0)     = make_float2(v0.x, v0.y);
            *reinterpret_cast<float2*>(out + f0 + 2) = make_float2(v0.z, v0.w);
        }
        if (f1 + 4 <= cap_f) {
            *reinterpret_cast<float2*>(out + f1)     = make_float2(v1.x, v1.y);
            *reinterpret_cast<float2*>(out + f1 + 2) = make_float2(v1.z, v1.w);
        }
    }
}

extern "C" void kernel_launch(void* const* d_in, const int* in_sizes, int n_in,
                              void* d_out, int out_size)
{
    if (!d_in || !d_out || n_in < 2) return;
    const float* Er = (const float*)d_in[0];
    const float* Ei = (const float*)d_in[1];
    if (!Er || !Ei) return;
    (void)in_sizes;

    const long long os = (long long)out_size;

    if (os == NCPLX || os == NCPLX * 4) {
        dim3 grid((NPAIR + PPB - 1) / PPB, BATCH);   // 40 x 128
        sofeat_pair_kernel<<<grid, TPB>>>(Er, Ei, (float2*)d_out);
    } else if (os == NFLT || os == NFLT * 4) {
        dim3 grid((NTRIP + TBLK - 1) / TBLK, BATCH);
        sofeat_full_kernel<<<grid, TPB>>>(Er, Ei, (float*)d_out, (size_t)NFLT);
    } else {
        size_t cap = (os > 0) ? (size_t)os : 0;
        if (cap > (size_t)NFLT) cap = (size_t)NFLT;
        dim3 grid((NTRIP + TBLK - 1) / TBLK, BATCH);
        sofeat_full_kernel<<<grid, TPB>>>(Er, Ei, (float*)d_out, cap);
    }
}